// round 10
// baseline (speedup 1.0000x reference)
#include <cuda_runtime.h>
#include <cuda_bf16.h>

#define NHEADS 512
#define NK     64
#define SEQ    2048
#define NFFT   4096
#define NB     16
#define PITCH  272   // transpose pitch: 16*17, conflict-free for both patterns

typedef unsigned long long ull;

// Filter spectra, packed complex (lo=re, hi=im), layout [h][q*256+t]
__device__ ull d_Fhat[NHEADS * NFFT];

// ---------------------------------------------------------------------------
// Packed f32x2 complex helpers (value = ull, lo 32b = re, hi 32b = im)
// ---------------------------------------------------------------------------
__device__ __forceinline__ ull pk2(float x, float y) {
    ull r; asm("mov.b64 %0, {%1, %2};" : "=l"(r) : "f"(x), "f"(y)); return r;
}
__device__ __forceinline__ void unpk2(ull a, float& x, float& y) {
    asm("mov.b64 {%0, %1}, %2;" : "=f"(x), "=f"(y) : "l"(a));
}
__device__ __forceinline__ ull padd(ull a, ull b) {
    ull r; asm("add.rn.f32x2 %0, %1, %2;" : "=l"(r) : "l"(a), "l"(b)); return r;
}
__device__ __forceinline__ ull psub(ull a, ull b) {   // a - b via fma(b, -1, a)
    const ull m1 = 0xBF800000BF800000ULL;
    ull r; asm("fma.rn.f32x2 %0, %1, %2, %3;" : "=l"(r) : "l"(b), "l"(m1), "l"(a)); return r;
}
__device__ __forceinline__ float fneg(float x) {
    return __int_as_float(__float_as_int(x) ^ 0x80000000);
}
template<int INV>
__device__ __forceinline__ ull pmulj(ull a) {
    float x, y; unpk2(a, x, y);
    return INV ? pk2(fneg(y), x) : pk2(y, fneg(x));
}
__device__ __forceinline__ ull pcmulf(ull a, float wx, float wy) {
    float x, y; unpk2(a, x, y);
    return pk2(fmaf(x, wx, -(y * wy)), fmaf(x, wy, y * wx));
}

template<int INV>
__device__ __forceinline__ void bfly4p(ull& x0, ull& x1, ull& x2, ull& x3) {
    ull ac = padd(x0, x2), amc = psub(x0, x2);
    ull bd = padd(x1, x3), bmd = psub(x1, x3);
    ull jb = pmulj<INV>(bmd);
    x0 = padd(ac, bd);  x2 = psub(ac, bd);
    x1 = padd(amc, jb); x3 = psub(amc, jb);
}

// half-output butterfly: only out0/out1 produced
template<int INV>
__device__ __forceinline__ void bfly4p_half(ull& x0, ull& x1, ull x2, ull x3) {
    ull ac = padd(x0, x2), amc = psub(x0, x2);
    ull bd = padd(x1, x3), bmd = psub(x1, x3);
    ull jb = pmulj<INV>(bmd);
    x0 = padd(ac, bd);
    x1 = padd(amc, jb);
}

template<int INV>
__device__ __forceinline__ void tw16(ull* u) {
    const float C1 = 0.9238795325112867f, S1 = 0.3826834323650898f, R = 0.7071067811865476f;
    const float s = INV ? 1.0f : -1.0f;
    u[5]  = pcmulf(u[5],   C1,  s * S1);
    u[6]  = pcmulf(u[6],    R,  s * R);
    u[7]  = pcmulf(u[7],   S1,  s * C1);
    u[9]  = pcmulf(u[9],    R,  s * R);
    u[10] = pmulj<INV>(u[10]);
    u[11] = pcmulf(u[11],  -R,  s * R);
    u[13] = pcmulf(u[13],  S1,  s * C1);
    u[14] = pcmulf(u[14],  -R,  s * R);
    u[15] = pcmulf(u[15], -C1, -s * S1);
}

template<int INV>
__device__ __forceinline__ void dft16p(ull* x) {
    ull u[16];
    #pragma unroll
    for (int n1 = 0; n1 < 4; n1++) {
        ull a = x[n1], b = x[n1 + 4], c = x[n1 + 8], d = x[n1 + 12];
        bfly4p<INV>(a, b, c, d);
        u[n1 * 4 + 0] = a; u[n1 * 4 + 1] = b; u[n1 * 4 + 2] = c; u[n1 * 4 + 3] = d;
    }
    tw16<INV>(u);
    #pragma unroll
    for (int k1 = 0; k1 < 4; k1++) {
        ull a = u[k1], b = u[4 + k1], c = u[8 + k1], d = u[12 + k1];
        bfly4p<INV>(a, b, c, d);
        x[k1] = a; x[k1 + 4] = b; x[k1 + 8] = c; x[k1 + 12] = d;
    }
}

// Inverse 16-pt DFT producing only outputs 0..7 (final inv stage).
__device__ __forceinline__ void dft16p_half(ull* x) {
    ull u[16];
    #pragma unroll
    for (int n1 = 0; n1 < 4; n1++) {
        ull a = x[n1], b = x[n1 + 4], c = x[n1 + 8], d = x[n1 + 12];
        bfly4p<1>(a, b, c, d);
        u[n1 * 4 + 0] = a; u[n1 * 4 + 1] = b; u[n1 * 4 + 2] = c; u[n1 * 4 + 3] = d;
    }
    tw16<1>(u);
    #pragma unroll
    for (int k1 = 0; k1 < 4; k1++) {
        ull a = u[k1], b = u[4 + k1];
        bfly4p_half<1>(a, b, u[8 + k1], u[12 + k1]);
        x[k1] = a; x[k1 + 4] = b;
    }
}

// Forward 16-pt DFT with x[8..15] == 0 (only x[0..7] read; all 16 written).
__device__ __forceinline__ void dft16ph(ull* x) {
    ull u[16];
    #pragma unroll
    for (int n1 = 0; n1 < 4; n1++) {
        ull a = x[n1], b = x[n1 + 4];      // c = d = 0
        ull jb = pmulj<0>(b);
        u[n1 * 4 + 0] = padd(a, b);
        u[n1 * 4 + 2] = psub(a, b);
        u[n1 * 4 + 1] = padd(a, jb);
        u[n1 * 4 + 3] = psub(a, jb);
    }
    tw16<0>(u);
    #pragma unroll
    for (int k1 = 0; k1 < 4; k1++) {
        ull a = u[k1], b = u[4 + k1], c = u[8 + k1], d = u[12 + k1];
        bfly4p<0>(a, b, c, d);
        x[k1] = a; x[k1 + 4] = b; x[k1 + 8] = c; x[k1 + 12] = d;
    }
}

__device__ __forceinline__ void twchain(ull* r, float wx, float wy) {
    float px = wx, py = wy;
    #pragma unroll
    for (int q = 1; q < 16; q++) {
        r[q] = pcmulf(r[q], px, py);
        float nx = px * wx - py * wy;
        float ny = px * wy + py * wx;
        px = nx; py = ny;
    }
}

#define ANG1 (-1.5339807878856412e-3f)   // -2*pi/4096
#define ANG2 (-2.4543692606170259e-2f)   // -2*pi/256

// ---------------------------------------------------------------------------
// N=4096 radix-16 FFT, 256 threads, 16 packed complex in registers/thread.
// ---------------------------------------------------------------------------
__device__ __forceinline__ void fft4096_fwd(ull* r, ull* sh, int t) {
    const int o = t & 15, b = t >> 4;
    dft16ph(r);
    { float sy, cx; __sincosf(ANG1 * (float)t, &sy, &cx); twchain(r, cx, sy); }
    #pragma unroll
    for (int q = 0; q < 16; q++) sh[PITCH * q + t] = r[q];
    __syncthreads();
    #pragma unroll
    for (int m = 0; m < 16; m++) r[m] = sh[PITCH * b + 16 * m + o];
    dft16p<0>(r);
    { float sy, cx; __sincosf(ANG2 * (float)o, &sy, &cx); twchain(r, cx, sy); }
    __syncthreads();
    #pragma unroll
    for (int q = 0; q < 16; q++) sh[PITCH * b + 17 * q + o] = r[q];
    __syncthreads();
    #pragma unroll
    for (int j = 0; j < 16; j++) r[j] = sh[PITCH * b + 17 * o + j];
    dft16p<0>(r);
}

__device__ __forceinline__ void fft4096_inv(ull* r, ull* sh, int t) {
    const int o = t & 15, b = t >> 4;
    dft16p<1>(r);
    __syncthreads();
    #pragma unroll
    for (int j = 0; j < 16; j++) sh[PITCH * b + 17 * o + j] = r[j];
    __syncthreads();
    #pragma unroll
    for (int q = 0; q < 16; q++) r[q] = sh[PITCH * b + 17 * q + o];
    { float sy, cx; __sincosf(-ANG2 * (float)o, &sy, &cx); twchain(r, cx, sy); }
    dft16p<1>(r);
    __syncthreads();
    #pragma unroll
    for (int m = 0; m < 16; m++) sh[PITCH * b + 16 * m + o] = r[m];
    __syncthreads();
    #pragma unroll
    for (int q = 0; q < 16; q++) r[q] = sh[PITCH * q + t];
    { float sy, cx; __sincosf(-ANG1 * (float)t, &sy, &cx); twchain(r, cx, sy); }
    dft16p_half(r);
}

// ---------------------------------------------------------------------------
// K1: filter build via impulse-response DOUBLING + fused forward FFT.
//   h_0 = 1;  h_t = sum_{i<64} w_i h_{t-1-i}
//   level s: c_m = sum_i w_i hp[s+m-1-i]  (frontier zeros make this exact),
//            h_{s+r} = sum_{m<64} c_m h_{r-m}   (r = 0..s-1)
//   f_t = sum_i g_i h_{t-i}  -> directly into FFT registers.
// ---------------------------------------------------------------------------
__global__ __launch_bounds__(256) void filter_fft_kernel(const float* __restrict__ kin) {
    __shared__ float sw[64], sg[64], spart[2], swtot[2];
    __shared__ float hp[64 + SEQ];   // hp[64+t] = h_t ; hp[0..63] = 0
    __shared__ float OO[128];        // OO[64+m] = c_m ; OO[0..63] = 0
    __shared__ ull  exch[16 * PITCH];

    const int tid = threadIdx.x;
    const int hh  = blockIdx.x;

    // zero padded arrays (frontier zeros are load-bearing)
    #pragma unroll
    for (int i = tid; i < 64 + SEQ; i += 256) hp[i] = 0.f;
    if (tid < 128) OO[tid] = 0.f;

    // ---- prep: kn, prefix-product P, w, g  (threads 0..63)
    float kv = 0.f, kc = 0.f;
    if (tid < 64) {
        kv = kin[hh * NK + tid];
        kc = fminf(fmaxf(kv, 0.0625f), 1.0f);
        float v = kc;
        #pragma unroll
        for (int o = 16; o; o >>= 1) v += __shfl_xor_sync(0xffffffffu, v, o);
        if ((tid & 31) == 0) spart[tid >> 5] = v;
    }
    __syncthreads();
    float kn = 0.f, opk = 1.f, sc = 1.f;
    if (tid < 64) {
        kn  = kc / (spart[0] + spart[1]);
        opk = 1.0f + kn;
        sc  = opk;                       // inclusive prefix product of opk
        #pragma unroll
        for (int o = 1; o < 32; o <<= 1) {
            float tmp = __shfl_up_sync(0xffffffffu, sc, o);
            if ((tid & 31) >= o) sc *= tmp;
        }
        if ((tid & 31) == 31) swtot[tid >> 5] = sc;
    }
    __syncthreads();
    if (tid < 64) {
        if (tid >= 32) sc *= swtot[0];
        float P  = opk / sc;             // = 1 / prod_{j<tid} (1+kn_j)
        float m0 = (tid < 63) ? kn / opk : 1.0f;
        sw[tid] = m0 * P;
        sg[tid] = kv * P * (1.0f / NFFT);
        if (tid == 0) hp[64] = 1.0f;     // h_0
    }
    __syncthreads();

    // ---- doubling levels s = 1, 2, 4, ..., 1024
    for (int s = 1; s < SEQ; s <<= 1) {
        if (tid < 64) {
            const float* base = &hp[64 + s + tid - 1];
            float a0 = 0.f, a1 = 0.f, a2 = 0.f, a3 = 0.f;
            #pragma unroll
            for (int i = 0; i < 64; i += 4) {
                a0 += sw[i + 0] * base[-i - 0];
                a1 += sw[i + 1] * base[-i - 1];
                a2 += sw[i + 2] * base[-i - 2];
                a3 += sw[i + 3] * base[-i - 3];
            }
            OO[64 + tid] = (a0 + a1) + (a2 + a3);
        }
        __syncthreads();
        for (int r = tid; r < s; r += 256) {
            const float* hb = &hp[64 + r];
            float a0 = 0.f, a1 = 0.f, a2 = 0.f, a3 = 0.f;
            #pragma unroll
            for (int m = 0; m < 64; m += 4) {
                a0 += OO[64 + m + 0] * hb[-m - 0];
                a1 += OO[64 + m + 1] * hb[-m - 1];
                a2 += OO[64 + m + 2] * hb[-m - 2];
                a3 += OO[64 + m + 3] * hb[-m - 3];
            }
            hp[64 + s + r] = (a0 + a1) + (a2 + a3);
        }
        __syncthreads();
    }

    // ---- f = g (*) h straight into FFT registers (padding handles t<63)
    ull rg[16];
    #pragma unroll
    for (int q = 0; q < 8; q++) {
        const int t = tid + 256 * q;
        const float* hb = &hp[64 + t];
        float a0 = 0.f, a1 = 0.f, a2 = 0.f, a3 = 0.f;
        #pragma unroll
        for (int i = 0; i < 64; i += 4) {
            a0 += sg[i + 0] * hb[-i - 0];
            a1 += sg[i + 1] * hb[-i - 1];
            a2 += sg[i + 2] * hb[-i - 2];
            a3 += sg[i + 3] * hb[-i - 3];
        }
        rg[q] = pk2((a0 + a1) + (a2 + a3), 0.f);
    }

    fft4096_fwd(rg, exch, tid);

    #pragma unroll
    for (int q = 0; q < 16; q++)
        d_Fhat[(size_t)hh * NFFT + q * 256 + tid] = rg[q];
}

// ---------------------------------------------------------------------------
// K2: FFT convolution, two batches packed per complex FFT.
// ---------------------------------------------------------------------------
__global__ __launch_bounds__(256, 4) void conv_kernel(const float* __restrict__ u,
                                                      float* __restrict__ y) {
    __shared__ ull exch[16 * PITCH];
    ull r[16];
    const int t  = threadIdx.x;
    const int h  = blockIdx.y;
    const int bp = blockIdx.x;
    const float* u0 = u + ((size_t)(2 * bp) * NHEADS + h) * SEQ;
    const float* u1 = u0 + (size_t)NHEADS * SEQ;

    #pragma unroll
    for (int q = 0; q < 8; q++) {
        int idx = t + 256 * q;
        r[q] = pk2(__ldg(&u0[idx]), __ldg(&u1[idx]));
    }

    fft4096_fwd(r, exch, t);

    const ull* Fh = d_Fhat + (size_t)h * NFFT;
    #pragma unroll
    for (int q = 0; q < 16; q++) {
        float fx, fy; unpk2(__ldg(&Fh[q * 256 + t]), fx, fy);
        r[q] = pcmulf(r[q], fx, fy);
    }

    fft4096_inv(r, exch, t);

    float* y0 = y + ((size_t)(2 * bp) * NHEADS + h) * SEQ;
    float* y1 = y0 + (size_t)NHEADS * SEQ;
    #pragma unroll
    for (int m = 0; m < 8; m++) {
        int idx = t + 256 * m;
        float a, b; unpk2(r[m], a, b);
        y0[idx] = a;
        y1[idx] = b;
    }
}

// ---------------------------------------------------------------------------
extern "C" void kernel_launch(void* const* d_in, const int* in_sizes, int n_in,
                              void* d_out, int out_size) {
    const float* u = (const float*)d_in[0];
    const float* k = (const float*)d_in[1];
    if (n_in >= 2 && in_sizes[0] < in_sizes[1]) {
        const float* t = u; u = k; k = t;
    }
    float* y = (float*)d_out;

    filter_fft_kernel<<<NHEADS, 256>>>(k);
    conv_kernel<<<dim3(NB / 2, NHEADS), 256>>>(u, y);
}